// round 1
// baseline (speedup 1.0000x reference)
#include <cuda_runtime.h>
#include <math.h>

#define HID 4096
#define SEQ 2048
#define NH 32
#define HD 128

// Scratch (static device allocations — no cudaMalloc allowed)
__device__ float g_Q[SEQ * HID];
__device__ float g_K[SEQ * HID];
__device__ float g_V[SEQ * HID];
__device__ float g_A[SEQ * HID];

// ---------------------------------------------------------------------------
// GEMM (NT): C[M,N] = A[M,K] * B[N,K]^T  (both operands K-contiguous, row-major)
// 128x128 tile, BK=16, 256 threads, 8x8 per-thread microtile.
// M,N,K assumed multiples of 128/16 (true here: 2048/4096/4096).
// ---------------------------------------------------------------------------
__global__ __launch_bounds__(256) void gemm_nt(const float* __restrict__ A,
                                               const float* __restrict__ B,
                                               float* __restrict__ C,
                                               int M, int N, int K) {
    const int BM = 128, BN = 128, BK = 16;
    __shared__ float As[BK][BM];
    __shared__ float Bs[BK][BN];

    int tid = threadIdx.x;
    int bm = blockIdx.y * BM;
    int bn = blockIdx.x * BN;
    int ty = tid / 16;       // 0..15 -> rows ty*8..ty*8+7
    int tx = tid % 16;       // 0..15 -> cols tx*8..tx*8+7

    float acc[8][8];
#pragma unroll
    for (int i = 0; i < 8; i++)
#pragma unroll
        for (int j = 0; j < 8; j++) acc[i][j] = 0.f;

    // Tile load mapping: 128 rows x 16 cols = 512 float4; thread covers 2.
    int lr0 = tid >> 2;            // row 0..63
    int lc0 = (tid & 3) << 2;      // col 0,4,8,12

    for (int k0 = 0; k0 < K; k0 += BK) {
#pragma unroll
        for (int s = 0; s < 2; s++) {
            int r = lr0 + s * 64;
            float4 va = *(const float4*)&A[(long)(bm + r) * K + k0 + lc0];
            As[lc0 + 0][r] = va.x; As[lc0 + 1][r] = va.y;
            As[lc0 + 2][r] = va.z; As[lc0 + 3][r] = va.w;
            float4 vb = *(const float4*)&B[(long)(bn + r) * K + k0 + lc0];
            Bs[lc0 + 0][r] = vb.x; Bs[lc0 + 1][r] = vb.y;
            Bs[lc0 + 2][r] = vb.z; Bs[lc0 + 3][r] = vb.w;
        }
        __syncthreads();

#pragma unroll
        for (int kk = 0; kk < BK; kk++) {
            float a[8], b[8];
            *(float4*)&a[0] = *(float4*)&As[kk][ty * 8];
            *(float4*)&a[4] = *(float4*)&As[kk][ty * 8 + 4];
            *(float4*)&b[0] = *(float4*)&Bs[kk][tx * 8];
            *(float4*)&b[4] = *(float4*)&Bs[kk][tx * 8 + 4];
#pragma unroll
            for (int i = 0; i < 8; i++)
#pragma unroll
                for (int j = 0; j < 8; j++)
                    acc[i][j] = fmaf(a[i], b[j], acc[i][j]);
        }
        __syncthreads();
    }

#pragma unroll
    for (int i = 0; i < 8; i++) {
        long r = bm + ty * 8 + i;
#pragma unroll
        for (int j = 0; j < 8; j += 4) {
            float4 v = make_float4(acc[i][j], acc[i][j + 1], acc[i][j + 2], acc[i][j + 3]);
            *(float4*)&C[r * N + bn + tx * 8 + j] = v;
        }
    }
}

// ---------------------------------------------------------------------------
// MsPoE RoPE: per-head compressed position, reversed head order.
// grid = SEQ*NH blocks, 64 threads (thread d handles pair (d, d+64)).
// ---------------------------------------------------------------------------
__global__ void rope_kernel(const int* __restrict__ pos_ids) {
    int b = blockIdx.x;
    int s = b / NH;
    int h = b % NH;
    int d = threadIdx.x;   // 0..63

    int r = NH - 1 - h;    // reversed head order
    float ratio = 1.0f + (3.0f - 1.0f) * ((float)r / (float)NH);
    float pos = (float)pos_ids[s];
    float t = pos / ratio;
    // inv_freq = 10000^(-2d/128) = 2^(-(2d/128)*log2(10000))
    float inv_freq = exp2f(-((float)(2 * d) / (float)HD) * 13.287712379549449f);
    float ang = t * inv_freq;
    float sn, cs;
    sincosf(ang, &sn, &cs);

    long base = (long)s * HID + h * HD;
    float q0 = g_Q[base + d], q1 = g_Q[base + d + 64];
    g_Q[base + d]      = q0 * cs - q1 * sn;
    g_Q[base + d + 64] = q1 * cs + q0 * sn;
    float k0 = g_K[base + d], k1 = g_K[base + d + 64];
    g_K[base + d]      = k0 * cs - k1 * sn;
    g_K[base + d + 64] = k1 * cs + k0 * sn;
}

// ---------------------------------------------------------------------------
// Causal flash attention, fp32. BQ=BKV=64, D=128, 256 threads.
// Q/K staged k-major ([128][64]) in smem for conflict-free LDS.128.
// ---------------------------------------------------------------------------
#define PSTRIDE 68
#define FLASH_SMEM ((128 * 64 + 128 * 64 + 64 * 128 + 64 * PSTRIDE) * 4)

__global__ __launch_bounds__(256) void flash_kernel() {
    extern __shared__ float sm[];
    float* Qt = sm;                 // [128][64]  (kk-major)
    float* Kt = Qt + 128 * 64;      // [128][64]
    float* Vs = Kt + 128 * 64;      // [64][128]  (row-major)
    float* Ps = Vs + 64 * 128;      // [64][PSTRIDE]

    int h = blockIdx.y;
    int qt = 31 - blockIdx.x;       // large tiles scheduled first
    int q0 = qt * 64;
    int tid = threadIdx.x;
    int ty = tid / 16;              // rows ty*4..ty*4+3
    int tx = tid % 16;              // score cols tx*4..+3 ; out cols tx*8..+7

    // Load Q tile transposed (64 rows x 128 d -> Qt[d][row])
    for (int idx = tid; idx < 2048; idx += 256) {
        int r = idx >> 5;
        int c4 = (idx & 31) << 2;
        float4 v = *(const float4*)&g_Q[(long)(q0 + r) * HID + h * HD + c4];
        Qt[(c4 + 0) * 64 + r] = v.x;
        Qt[(c4 + 1) * 64 + r] = v.y;
        Qt[(c4 + 2) * 64 + r] = v.z;
        Qt[(c4 + 3) * 64 + r] = v.w;
    }

    float m[4], l[4], acc[4][8];
#pragma unroll
    for (int i = 0; i < 4; i++) {
        m[i] = -INFINITY;
        l[i] = 0.f;
#pragma unroll
        for (int c = 0; c < 8; c++) acc[i][c] = 0.f;
    }

    const float sscale = 0.08838834764831845f;  // 1/sqrt(128)

    for (int kt = 0; kt <= qt; kt++) {
        int k0 = kt * 64;
        __syncthreads();  // previous PV done with Vs/Ps; Q load visible

        for (int idx = tid; idx < 2048; idx += 256) {
            int r = idx >> 5;
            int c4 = (idx & 31) << 2;
            long gb = (long)(k0 + r) * HID + h * HD + c4;
            float4 kv = *(const float4*)&g_K[gb];
            Kt[(c4 + 0) * 64 + r] = kv.x;
            Kt[(c4 + 1) * 64 + r] = kv.y;
            Kt[(c4 + 2) * 64 + r] = kv.z;
            Kt[(c4 + 3) * 64 + r] = kv.w;
            float4 vv = *(const float4*)&g_V[gb];
            *(float4*)&Vs[r * 128 + c4] = vv;
        }
        __syncthreads();

        // ---- scores S = Q K^T (this thread: 4x4 microtile) ----
        float s[4][4];
#pragma unroll
        for (int i = 0; i < 4; i++)
#pragma unroll
            for (int j = 0; j < 4; j++) s[i][j] = 0.f;

#pragma unroll 4
        for (int kk = 0; kk < 128; kk++) {
            float4 qv = *(float4*)&Qt[kk * 64 + ty * 4];
            float4 kv = *(float4*)&Kt[kk * 64 + tx * 4];
            float qa[4] = {qv.x, qv.y, qv.z, qv.w};
            float ka[4] = {kv.x, kv.y, kv.z, kv.w};
#pragma unroll
            for (int i = 0; i < 4; i++)
#pragma unroll
                for (int j = 0; j < 4; j++)
                    s[i][j] = fmaf(qa[i], ka[j], s[i][j]);
        }

        // scale + causal mask (only diagonal tile needs it)
        bool diag = (kt == qt);
#pragma unroll
        for (int i = 0; i < 4; i++)
#pragma unroll
            for (int j = 0; j < 4; j++) {
                s[i][j] *= sscale;
                if (diag && (ty * 4 + i) < (tx * 4 + j)) s[i][j] = -INFINITY;
            }

        // ---- online softmax ----
        float rmax[4], rsum[4];
#pragma unroll
        for (int i = 0; i < 4; i++) {
            float v = fmaxf(fmaxf(s[i][0], s[i][1]), fmaxf(s[i][2], s[i][3]));
#pragma unroll
            for (int off = 8; off > 0; off >>= 1)
                v = fmaxf(v, __shfl_xor_sync(0xffffffffu, v, off));
            rmax[i] = v;
        }
#pragma unroll
        for (int i = 0; i < 4; i++) {
            float mnew = fmaxf(m[i], rmax[i]);
            float corr = __expf(m[i] - mnew);
            float p0 = __expf(s[i][0] - mnew);
            float p1 = __expf(s[i][1] - mnew);
            float p2 = __expf(s[i][2] - mnew);
            float p3 = __expf(s[i][3] - mnew);
            s[i][0] = p0; s[i][1] = p1; s[i][2] = p2; s[i][3] = p3;
            float rs = p0 + p1 + p2 + p3;
#pragma unroll
            for (int off = 8; off > 0; off >>= 1)
                rs += __shfl_xor_sync(0xffffffffu, rs, off);
            rsum[i] = rs;
            l[i] = l[i] * corr + rs;
            m[i] = mnew;
#pragma unroll
            for (int c = 0; c < 8; c++) acc[i][c] *= corr;
            // store P row slice
            *(float4*)&Ps[(ty * 4 + i) * PSTRIDE + tx * 4] =
                make_float4(p0, p1, p2, p3);
        }
        __syncthreads();

        // ---- O += P V ----
#pragma unroll 4
        for (int j = 0; j < 64; j++) {
            float4 v0 = *(float4*)&Vs[j * 128 + tx * 8];
            float4 v1 = *(float4*)&Vs[j * 128 + tx * 8 + 4];
#pragma unroll
            for (int i = 0; i < 4; i++) {
                float p = Ps[(ty * 4 + i) * PSTRIDE + j];
                acc[i][0] = fmaf(p, v0.x, acc[i][0]);
                acc[i][1] = fmaf(p, v0.y, acc[i][1]);
                acc[i][2] = fmaf(p, v0.z, acc[i][2]);
                acc[i][3] = fmaf(p, v0.w, acc[i][3]);
                acc[i][4] = fmaf(p, v1.x, acc[i][4]);
                acc[i][5] = fmaf(p, v1.y, acc[i][5]);
                acc[i][6] = fmaf(p, v1.z, acc[i][6]);
                acc[i][7] = fmaf(p, v1.w, acc[i][7]);
            }
        }
    }

    // epilogue: normalize + store
#pragma unroll
    for (int i = 0; i < 4; i++) {
        float inv = 1.0f / l[i];
        long base = (long)(q0 + ty * 4 + i) * HID + h * HD + tx * 8;
        float4 o0 = make_float4(acc[i][0] * inv, acc[i][1] * inv,
                                acc[i][2] * inv, acc[i][3] * inv);
        float4 o1 = make_float4(acc[i][4] * inv, acc[i][5] * inv,
                                acc[i][6] * inv, acc[i][7] * inv);
        *(float4*)&g_A[base] = o0;
        *(float4*)&g_A[base + 4] = o1;
    }
}

// ---------------------------------------------------------------------------
extern "C" void kernel_launch(void* const* d_in, const int* in_sizes, int n_in,
                              void* d_out, int out_size) {
    (void)in_sizes; (void)n_in; (void)out_size;
    const float* x   = (const float*)d_in[0];
    const int*   pos = (const int*)d_in[1];
    const float* wq  = (const float*)d_in[2];
    const float* wk  = (const float*)d_in[3];
    const float* wv  = (const float*)d_in[4];
    const float* wo  = (const float*)d_in[5];
    float* out = (float*)d_out;

    float *Q, *K, *V, *A;
    cudaGetSymbolAddress((void**)&Q, g_Q);
    cudaGetSymbolAddress((void**)&K, g_K);
    cudaGetSymbolAddress((void**)&V, g_V);
    cudaGetSymbolAddress((void**)&A, g_A);

    dim3 gg(HID / 128, SEQ / 128);  // (32, 16)
    gemm_nt<<<gg, 256>>>(x, wq, Q, SEQ, HID, HID);
    gemm_nt<<<gg, 256>>>(x, wk, K, SEQ, HID, HID);
    gemm_nt<<<gg, 256>>>(x, wv, V, SEQ, HID, HID);

    rope_kernel<<<SEQ * NH, 64>>>(pos);

    cudaFuncSetAttribute(flash_kernel,
                         cudaFuncAttributeMaxDynamicSharedMemorySize, FLASH_SMEM);
    flash_kernel<<<dim3(32, 32), 256, FLASH_SMEM>>>();

    gemm_nt<<<gg, 256>>>(A, wo, out, SEQ, HID, HID);
}

// round 3
// speedup vs baseline: 2.3306x; 2.3306x over previous
#include <cuda_runtime.h>
#include <math.h>

#define HID 4096
#define SEQ 2048
#define NH 32
#define HD 128

typedef unsigned int u32;

// Scratch (static device allocations — no cudaMalloc allowed)
__device__ float g_Q[SEQ * HID];
__device__ float g_K[SEQ * HID];
__device__ float g_V[SEQ * HID];
__device__ float g_A[SEQ * HID];

__device__ __forceinline__ u32 smem_u32(const void* p) {
    u32 a;
    asm("{ .reg .u64 t; cvta.to.shared.u64 t, %1; cvt.u32.u64 %0, t; }"
        : "=r"(a) : "l"(p));
    return a;
}
__device__ __forceinline__ void cp16(u32 dst, const void* src) {
    asm volatile("cp.async.cg.shared.global [%0], [%1], 16;\n" :: "r"(dst), "l"(src));
}
__device__ __forceinline__ u32 f2tf32(float f) {
    u32 r;
    asm("cvt.rna.tf32.f32 %0, %1;" : "=r"(r) : "f"(f));
    return r;
}
__device__ __forceinline__ void ldmx4(u32 addr, u32& r0, u32& r1, u32& r2, u32& r3) {
    asm volatile("ldmatrix.sync.aligned.m8n8.x4.shared.b16 {%0,%1,%2,%3}, [%4];"
                 : "=r"(r0), "=r"(r1), "=r"(r2), "=r"(r3) : "r"(addr));
}
__device__ __forceinline__ void mma_tf32(float* c, const u32* a, const u32* b) {
    asm volatile(
        "mma.sync.aligned.m16n8k8.row.col.f32.tf32.tf32.f32 "
        "{%0,%1,%2,%3}, {%4,%5,%6,%7}, {%8,%9}, {%0,%1,%2,%3};"
        : "+f"(c[0]), "+f"(c[1]), "+f"(c[2]), "+f"(c[3])
        : "r"(a[0]), "r"(a[1]), "r"(a[2]), "r"(a[3]), "r"(b[0]), "r"(b[1]));
}

// ===========================================================================
// TF32 mma.sync GEMM (NT): C[M,N] = A[M,K] * B[N,K]^T, fp32 in/out.
// BM=BN=128, BK=32. 256 threads = 8 warps (2 in M x 4 in N), warp tile 64x32.
// Smem rows padded to 36 floats (144B): conflict-free ldmatrix.
// 2-stage cp.async pipeline.
// ===========================================================================
#define GBM 128
#define GBN 128
#define GBK 32
#define ROWW 36                               // floats per smem row (pad)
#define TILE_F (128 * ROWW)                   // floats per tile (A or B)
#define STG_F (2 * TILE_F)                    // floats per stage (A+B)
#define GEMM_SMEM (2 * STG_F * 4)             // bytes, 2 stages = 73728

__device__ __forceinline__ void gemm_stage_load(
    const float* __restrict__ A, const float* __restrict__ Bw, int K,
    int bm, int bn, int k0, u32 sA, u32 sB, int tid)
{
#pragma unroll
    for (int i = 0; i < 4; i++) {                 // A: 1024 x 16B chunks
        int c = tid + i * 256;
        int r = c >> 3, cb = (c & 7) << 4;
        cp16(sA + r * 144 + cb, (const char*)(A + (long)(bm + r) * K + k0) + cb);
    }
#pragma unroll
    for (int i = 0; i < 4; i++) {                 // B: 1024 x 16B chunks
        int c = tid + i * 256;
        int r = c >> 3, cb = (c & 7) << 4;
        cp16(sB + r * 144 + cb, (const char*)(Bw + (long)(bn + r) * K + k0) + cb);
    }
}

__global__ __launch_bounds__(256, 2) void gemm_tf32(const float* __restrict__ A,
                                                    const float* __restrict__ Bw,
                                                    float* __restrict__ C,
                                                    int M, int N, int K) {
    extern __shared__ float sm[];
    u32 sbase = smem_u32(sm);
    int tid = threadIdx.x;
    int wid = tid >> 5, lane = tid & 31;
    int wm = wid & 1, wn = wid >> 1;              // 2 x 4 warp grid
    int bm = blockIdx.y * GBM;
    int bn = blockIdx.x * GBN;
    const int KT = K / GBK;

    // per-thread ldmatrix base offsets (within a tile, bytes)
    // A frag: row = mrow0 + (lane&15), col4 = (lane>>4)*16B
    u32 a_off = (u32)((wm * 64 + (lane & 15)) * 144 + (lane >> 4) * 16);
    // B frag pair: row = n0 + (lane&7) + ((lane&16)?8:0), col = ((lane&8)?4:0)
    u32 b_off = (u32)((wn * 32 + (lane & 7) + ((lane & 16) ? 8 : 0)) * 144 +
                      ((lane & 8) ? 16 : 0));

    float acc[4][4][4];                            // [mt][nt][4]
#pragma unroll
    for (int i = 0; i < 4; i++)
#pragma unroll
        for (int j = 0; j < 4; j++)
#pragma unroll
            for (int c = 0; c < 4; c++) acc[i][j][c] = 0.f;

    u32 stA[2] = {sbase, sbase + STG_F * 4};
    u32 stB[2] = {sbase + TILE_F * 4, sbase + STG_F * 4 + TILE_F * 4};

    gemm_stage_load(A, Bw, K, bm, bn, 0, stA[0], stB[0], tid);
    asm volatile("cp.async.commit_group;\n" ::: "memory");

    for (int kt = 0; kt < KT; kt++) {
        int slot = kt & 1;
        asm volatile("cp.async.wait_group 0;\n" ::: "memory");
        __syncthreads();
        if (kt + 1 < KT) {
            gemm_stage_load(A, Bw, K, bm, bn, (kt + 1) * GBK,
                            stA[slot ^ 1], stB[slot ^ 1], tid);
            asm volatile("cp.async.commit_group;\n" ::: "memory");
        }

        u32 aBase = stA[slot] + a_off;
        u32 bBase = stB[slot] + b_off;
#pragma unroll
        for (int ks = 0; ks < 4; ks++) {           // k = ks*8
            u32 af[4][4], bf[2][4];
#pragma unroll
            for (int mt = 0; mt < 4; mt++) {
                ldmx4(aBase + mt * (16 * 144) + ks * 32,
                      af[mt][0], af[mt][1], af[mt][2], af[mt][3]);
#pragma unroll
                for (int r = 0; r < 4; r++) af[mt][r] = f2tf32(__uint_as_float(af[mt][r]));
            }
#pragma unroll
            for (int np = 0; np < 2; np++) {       // each covers 2 n-tiles
                ldmx4(bBase + np * (16 * 144) + ks * 32,
                      bf[np][0], bf[np][1], bf[np][2], bf[np][3]);
#pragma unroll
                for (int r = 0; r < 4; r++) bf[np][r] = f2tf32(__uint_as_float(bf[np][r]));
            }
#pragma unroll
            for (int mt = 0; mt < 4; mt++)
#pragma unroll
                for (int nt = 0; nt < 4; nt++)
                    mma_tf32(acc[mt][nt], af[mt], &bf[nt >> 1][(nt & 1) * 2]);
        }
        __syncthreads();
    }

    // epilogue: c0,c1 at (row, 2c), (row, 2c+1); c2,c3 at (row+8, ...)
    int r0 = bm + wm * 64 + (lane >> 2);
    int c0 = bn + wn * 32 + (lane & 3) * 2;
#pragma unroll
    for (int mt = 0; mt < 4; mt++) {
#pragma unroll
        for (int nt = 0; nt < 4; nt++) {
            long r = r0 + mt * 16;
            int c = c0 + nt * 8;
            *(float2*)&C[r * N + c]       = make_float2(acc[mt][nt][0], acc[mt][nt][1]);
            *(float2*)&C[(r + 8) * N + c] = make_float2(acc[mt][nt][2], acc[mt][nt][3]);
        }
    }
}

// ---------------------------------------------------------------------------
// MsPoE RoPE: per-head compressed position, reversed head order.
// ---------------------------------------------------------------------------
__global__ void rope_kernel(const int* __restrict__ pos_ids) {
    int b = blockIdx.x;
    int s = b / NH;
    int h = b % NH;
    int d = threadIdx.x;   // 0..63

    int r = NH - 1 - h;
    float ratio = 1.0f + (3.0f - 1.0f) * ((float)r / (float)NH);
    float pos = (float)pos_ids[s];
    float t = pos / ratio;
    float inv_freq = exp2f(-((float)(2 * d) / (float)HD) * 13.287712379549449f);
    float ang = t * inv_freq;
    float sn, cs;
    sincosf(ang, &sn, &cs);

    long base = (long)s * HID + h * HD;
    float q0 = g_Q[base + d], q1 = g_Q[base + d + 64];
    g_Q[base + d]      = q0 * cs - q1 * sn;
    g_Q[base + d + 64] = q1 * cs + q0 * sn;
    float k0 = g_K[base + d], k1 = g_K[base + d + 64];
    g_K[base + d]      = k0 * cs - k1 * sn;
    g_K[base + d + 64] = k1 * cs + k0 * sn;
}

// ---------------------------------------------------------------------------
// Causal flash attention, fp32 SIMT. BQ=BKV=64, D=128, 256 threads.
// ---------------------------------------------------------------------------
#define PSTRIDE 68
#define FLASH_SMEM ((128 * 64 + 128 * 64 + 64 * 128 + 64 * PSTRIDE) * 4)

__global__ __launch_bounds__(256) void flash_kernel() {
    extern __shared__ float smf[];
    float* Qt = smf;                // [128][64]
    float* Kt = Qt + 128 * 64;      // [128][64]
    float* Vs = Kt + 128 * 64;      // [64][128]
    float* Ps = Vs + 64 * 128;      // [64][PSTRIDE]

    int h = blockIdx.y;
    int qt = 31 - blockIdx.x;
    int q0 = qt * 64;
    int tid = threadIdx.x;
    int ty = tid / 16;
    int tx = tid % 16;

    for (int idx = tid; idx < 2048; idx += 256) {
        int r = idx >> 5;
        int c4 = (idx & 31) << 2;
        float4 v = *(const float4*)&g_Q[(long)(q0 + r) * HID + h * HD + c4];
        Qt[(c4 + 0) * 64 + r] = v.x;
        Qt[(c4 + 1) * 64 + r] = v.y;
        Qt[(c4 + 2) * 64 + r] = v.z;
        Qt[(c4 + 3) * 64 + r] = v.w;
    }

    float m[4], l[4], acc[4][8];
#pragma unroll
    for (int i = 0; i < 4; i++) {
        m[i] = -INFINITY;
        l[i] = 0.f;
#pragma unroll
        for (int c = 0; c < 8; c++) acc[i][c] = 0.f;
    }

    const float sscale = 0.08838834764831845f;

    for (int kt = 0; kt <= qt; kt++) {
        int k0 = kt * 64;
        __syncthreads();

        for (int idx = tid; idx < 2048; idx += 256) {
            int r = idx >> 5;
            int c4 = (idx & 31) << 2;
            long gb = (long)(k0 + r) * HID + h * HD + c4;
            float4 kv = *(const float4*)&g_K[gb];
            Kt[(c4 + 0) * 64 + r] = kv.x;
            Kt[(c4 + 1) * 64 + r] = kv.y;
            Kt[(c4 + 2) * 64 + r] = kv.z;
            Kt[(c4 + 3) * 64 + r] = kv.w;
            float4 vv = *(const float4*)&g_V[gb];
            *(float4*)&Vs[r * 128 + c4] = vv;
        }
        __syncthreads();

        float s[4][4];
#pragma unroll
        for (int i = 0; i < 4; i++)
#pragma unroll
            for (int j = 0; j < 4; j++) s[i][j] = 0.f;

#pragma unroll 4
        for (int kk = 0; kk < 128; kk++) {
            float4 qv = *(float4*)&Qt[kk * 64 + ty * 4];
            float4 kv = *(float4*)&Kt[kk * 64 + tx * 4];
            float qa[4] = {qv.x, qv.y, qv.z, qv.w};
            float ka[4] = {kv.x, kv.y, kv.z, kv.w};
#pragma unroll
            for (int i = 0; i < 4; i++)
#pragma unroll
                for (int j = 0; j < 4; j++)
                    s[i][j] = fmaf(qa[i], ka[j], s[i][j]);
        }

        bool diag = (kt == qt);
#pragma unroll
        for (int i = 0; i < 4; i++)
#pragma unroll
            for (int j = 0; j < 4; j++) {
                s[i][j] *= sscale;
                if (diag && (ty * 4 + i) < (tx * 4 + j)) s[i][j] = -INFINITY;
            }

        float rmax[4];
#pragma unroll
        for (int i = 0; i < 4; i++) {
            float v = fmaxf(fmaxf(s[i][0], s[i][1]), fmaxf(s[i][2], s[i][3]));
#pragma unroll
            for (int off = 8; off > 0; off >>= 1)
                v = fmaxf(v, __shfl_xor_sync(0xffffffffu, v, off));
            rmax[i] = v;
        }
#pragma unroll
        for (int i = 0; i < 4; i++) {
            float mnew = fmaxf(m[i], rmax[i]);
            float corr = __expf(m[i] - mnew);
            float p0 = __expf(s[i][0] - mnew);
            float p1 = __expf(s[i][1] - mnew);
            float p2 = __expf(s[i][2] - mnew);
            float p3 = __expf(s[i][3] - mnew);
            float rs = p0 + p1 + p2 + p3;
#pragma unroll
            for (int off = 8; off > 0; off >>= 1)
                rs += __shfl_xor_sync(0xffffffffu, rs, off);
            l[i] = l[i] * corr + rs;
            m[i] = mnew;
#pragma unroll
            for (int c = 0; c < 8; c++) acc[i][c] *= corr;
            *(float4*)&Ps[(ty * 4 + i) * PSTRIDE + tx * 4] =
                make_float4(p0, p1, p2, p3);
        }
        __syncthreads();

#pragma unroll 4
        for (int j = 0; j < 64; j++) {
            float4 v0 = *(float4*)&Vs[j * 128 + tx * 8];
            float4 v1 = *(float4*)&Vs[j * 128 + tx * 8 + 4];
#pragma unroll
            for (int i = 0; i < 4; i++) {
                float p = Ps[(ty * 4 + i) * PSTRIDE + j];
                acc[i][0] = fmaf(p, v0.x, acc[i][0]);
                acc[i][1] = fmaf(p, v0.y, acc[i][1]);
                acc[i][2] = fmaf(p, v0.z, acc[i][2]);
                acc[i][3] = fmaf(p, v0.w, acc[i][3]);
                acc[i][4] = fmaf(p, v1.x, acc[i][4]);
                acc[i][5] = fmaf(p, v1.y, acc[i][5]);
                acc[i][6] = fmaf(p, v1.z, acc[i][6]);
                acc[i][7] = fmaf(p, v1.w, acc[i][7]);
            }
        }
    }

#pragma unroll
    for (int i = 0; i < 4; i++) {
        float inv = 1.0f / l[i];
        long base = (long)(q0 + ty * 4 + i) * HID + h * HD + tx * 8;
        float4 o0 = make_float4(acc[i][0] * inv, acc[i][1] * inv,
                                acc[i][2] * inv, acc[i][3] * inv);
        float4 o1 = make_float4(acc[i][4] * inv, acc[i][5] * inv,
                                acc[i][6] * inv, acc[i][7] * inv);
        *(float4*)&g_A[base] = o0;
        *(float4*)&g_A[base + 4] = o1;
    }
}

// ---------------------------------------------------------------------------
extern "C" void kernel_launch(void* const* d_in, const int* in_sizes, int n_in,
                              void* d_out, int out_size) {
    (void)in_sizes; (void)n_in; (void)out_size;
    const float* x   = (const float*)d_in[0];
    const int*   pos = (const int*)d_in[1];
    const float* wq  = (const float*)d_in[2];
    const float* wk  = (const float*)d_in[3];
    const float* wv  = (const float*)d_in[4];
    const float* wo  = (const float*)d_in[5];
    float* out = (float*)d_out;

    float *Q, *K, *V, *A;
    cudaGetSymbolAddress((void**)&Q, g_Q);
    cudaGetSymbolAddress((void**)&K, g_K);
    cudaGetSymbolAddress((void**)&V, g_V);
    cudaGetSymbolAddress((void**)&A, g_A);

    cudaFuncSetAttribute(gemm_tf32,
                         cudaFuncAttributeMaxDynamicSharedMemorySize, GEMM_SMEM);
    dim3 gg(HID / GBN, SEQ / GBM);  // (32, 16)
    gemm_tf32<<<gg, 256, GEMM_SMEM>>>(x, wq, Q, SEQ, HID, HID);
    gemm_tf32<<<gg, 256, GEMM_SMEM>>>(x, wk, K, SEQ, HID, HID);
    gemm_tf32<<<gg, 256, GEMM_SMEM>>>(x, wv, V, SEQ, HID, HID);

    rope_kernel<<<SEQ * NH, 64>>>(pos);

    cudaFuncSetAttribute(flash_kernel,
                         cudaFuncAttributeMaxDynamicSharedMemorySize, FLASH_SMEM);
    flash_kernel<<<dim3(32, 32), 256, FLASH_SMEM>>>();

    gemm_tf32<<<gg, 256, GEMM_SMEM>>>(A, wo, out, SEQ, HID, HID);
}

// round 6
// speedup vs baseline: 8.1468x; 3.4955x over previous
#include <cuda_runtime.h>
#include <cuda_fp16.h>
#include <math.h>

#define HID 4096
#define SEQ 2048
#define NH 32
#define HD 128

typedef unsigned int u32;

// Static scratch (no cudaMalloc allowed)
__device__ __align__(256) __half g_Xh[SEQ * HID];
__device__ __align__(256) __half g_Wq[HID * HID];
__device__ __align__(256) __half g_Wk[HID * HID];
__device__ __align__(256) __half g_Wv[HID * HID];
__device__ __align__(256) __half g_Wo[HID * HID];
__device__ __align__(256) __half g_Qh[SEQ * HID];
__device__ __align__(256) __half g_Kh[SEQ * HID];
__device__ __align__(256) __half g_Vh[SEQ * HID];
__device__ __align__(256) __half g_Ah[SEQ * HID];

__device__ __forceinline__ u32 smem_u32(const void* p) {
    u32 a;
    asm("{ .reg .u64 t; cvta.to.shared.u64 t, %1; cvt.u32.u64 %0, t; }"
        : "=r"(a) : "l"(p));
    return a;
}
__device__ __forceinline__ void cp16(u32 dst, const void* src) {
    asm volatile("cp.async.cg.shared.global [%0], [%1], 16;\n" :: "r"(dst), "l"(src));
}
__device__ __forceinline__ void ldmx4(u32 addr, u32& r0, u32& r1, u32& r2, u32& r3) {
    asm volatile("ldmatrix.sync.aligned.m8n8.x4.shared.b16 {%0,%1,%2,%3}, [%4];"
                 : "=r"(r0), "=r"(r1), "=r"(r2), "=r"(r3) : "r"(addr));
}
__device__ __forceinline__ void ldmx4t(u32 addr, u32& r0, u32& r1, u32& r2, u32& r3) {
    asm volatile("ldmatrix.sync.aligned.m8n8.x4.trans.shared.b16 {%0,%1,%2,%3}, [%4];"
                 : "=r"(r0), "=r"(r1), "=r"(r2), "=r"(r3) : "r"(addr));
}
__device__ __forceinline__ void mma_h(float* c, const u32* a, const u32* b) {
    asm volatile(
        "mma.sync.aligned.m16n8k16.row.col.f32.f16.f16.f32 "
        "{%0,%1,%2,%3}, {%4,%5,%6,%7}, {%8,%9}, {%0,%1,%2,%3};"
        : "+f"(c[0]), "+f"(c[1]), "+f"(c[2]), "+f"(c[3])
        : "r"(a[0]), "r"(a[1]), "r"(a[2]), "r"(a[3]), "r"(b[0]), "r"(b[1]));
}
__device__ __forceinline__ u32 pack_h2(float a, float b) {
    __half2 h = __floats2half2_rn(a, b);
    return *reinterpret_cast<u32*>(&h);
}

// ---------------------------------------------------------------------------
__global__ void cvt_f2h(const float4* __restrict__ src, __half2* __restrict__ dst,
                        int n4) {
    int i = blockIdx.x * blockDim.x + threadIdx.x;
    if (i < n4) {
        float4 v = src[i];
        dst[2 * i]     = __floats2half2_rn(v.x, v.y);
        dst[2 * i + 1] = __floats2half2_rn(v.z, v.w);
    }
}

// ===========================================================================
// fp16 mma GEMM (NT): C[M,N] = A[M,K]h * B[N,K]h^T, fp32 accumulate.
// BM=BN=128, BK=64. 256 threads = 8 warps (2 x 4), warp tile 64x32.
// Warp's 32 cols = two 16-col chunks at n and n+64 (RoPE pairs local).
// ROPE: rotate fp32 accumulators before fp16 store (one 128-col tile = one head).
// ===========================================================================
#define ROWB 144
#define GTILE (128 * ROWB)
#define GSTG  (2 * GTILE)
#define GEMM_SMEM (2 * GSTG)                  // 73728

__device__ __forceinline__ void gemm_stage_load(
    const __half* __restrict__ A, const __half* __restrict__ Bw, int K,
    int bm, int bn, int k0, u32 sA, u32 sB, int tid)
{
#pragma unroll
    for (int i = 0; i < 4; i++) {
        int c = tid + i * 256;
        int r = c >> 3, cb = (c & 7) << 4;
        cp16(sA + r * ROWB + cb,
             (const char*)(A + (long)(bm + r) * K + k0) + cb);
    }
#pragma unroll
    for (int i = 0; i < 4; i++) {
        int c = tid + i * 256;
        int r = c >> 3, cb = (c & 7) << 4;
        cp16(sB + r * ROWB + cb,
             (const char*)(Bw + (long)(bn + r) * K + k0) + cb);
    }
}

template <typename OutT, int ROPE>
__global__ __launch_bounds__(256, 2) void gemm_h(const __half* __restrict__ A,
                                                 const __half* __restrict__ Bw,
                                                 OutT* __restrict__ C,
                                                 const int* __restrict__ pos,
                                                 int M, int N, int K) {
    extern __shared__ char smg[];
    u32 sbase = smem_u32(smg);
    int tid = threadIdx.x;
    int lane = tid & 31, wid = tid >> 5;
    int wm = wid & 1, wn = wid >> 1;
    int bm = blockIdx.y * 128;
    int bn = blockIdx.x * 128;
    const int KT = K / 64;

    u32 a_off = (u32)((wm * 64 + (lane & 15)) * ROWB + (lane >> 4) * 16);
    // B: warp covers n rows [wn*16, +16) and [wn*16+64, +16)
    u32 b_off = (u32)((wn * 16 + (lane & 7) + ((lane & 16) ? 8 : 0)) * ROWB +
                      ((lane & 8) ? 16 : 0));

    float acc[4][4][4];      // [mt][nt = (np<<1)|loc][q]
#pragma unroll
    for (int i = 0; i < 4; i++)
#pragma unroll
        for (int j = 0; j < 4; j++)
#pragma unroll
            for (int q = 0; q < 4; q++) acc[i][j][q] = 0.f;

    u32 stA[2] = {sbase, sbase + GSTG};
    u32 stB[2] = {sbase + GTILE, sbase + GSTG + GTILE};

    gemm_stage_load(A, Bw, K, bm, bn, 0, stA[0], stB[0], tid);
    asm volatile("cp.async.commit_group;\n" ::: "memory");

    for (int kt = 0; kt < KT; kt++) {
        int slot = kt & 1;
        asm volatile("cp.async.wait_group 0;\n" ::: "memory");
        __syncthreads();
        if (kt + 1 < KT) {
            gemm_stage_load(A, Bw, K, bm, bn, (kt + 1) * 64,
                            stA[slot ^ 1], stB[slot ^ 1], tid);
            asm volatile("cp.async.commit_group;\n" ::: "memory");
        }

        u32 aB = stA[slot] + a_off;
        u32 bB = stB[slot] + b_off;
#pragma unroll
        for (int ks = 0; ks < 4; ks++) {
            u32 af[4][4], bf[2][4];
#pragma unroll
            for (int mt = 0; mt < 4; mt++)
                ldmx4(aB + mt * (16 * ROWB) + ks * 32,
                      af[mt][0], af[mt][1], af[mt][2], af[mt][3]);
#pragma unroll
            for (int np = 0; np < 2; np++)
                ldmx4(bB + np * (64 * ROWB) + ks * 32,
                      bf[np][0], bf[np][1], bf[np][2], bf[np][3]);
#pragma unroll
            for (int mt = 0; mt < 4; mt++)
#pragma unroll
                for (int nt = 0; nt < 4; nt++)
                    mma_h(acc[mt][nt], af[mt], &bf[nt >> 1][(nt & 1) * 2]);
        }
    }

    int r0 = bm + wm * 64 + (lane >> 2);
    int cq0 = wn * 16 + (lane & 3) * 2;          // col within head, np=0 chunk

    if (ROPE) {
        int rh = NH - 1 - blockIdx.x;            // reversed head order
        float ratio_inv = 1.0f / (1.0f + 2.0f * ((float)rh / (float)NH));
        const float L2 = 13.287712379549449f;    // log2(10000)
#pragma unroll
        for (int mt = 0; mt < 4; mt++) {
#pragma unroll
            for (int t = 0; t < 2; t++) {
                int row = r0 + mt * 16 + t * 8;
                float tp = (float)pos[row] * ratio_inv;
#pragma unroll
                for (int loc = 0; loc < 2; loc++) {
#pragma unroll
                    for (int cq = 0; cq < 2; cq++) {
                        int d = cq0 + loc * 8 + cq;        // in [0,64)
                        float inv_freq = exp2f(-((float)d * (1.0f / 64.0f)) * L2);
                        float sn, cs;
                        sincosf(tp * inv_freq, &sn, &cs);
                        int q = t * 2 + cq;
                        float a = acc[mt][loc][q];         // d
                        float b = acc[mt][loc + 2][q];     // d + 64
                        acc[mt][loc][q]     = a * cs - b * sn;
                        acc[mt][loc + 2][q] = b * cs + a * sn;
                    }
                }
            }
        }
    }

#pragma unroll
    for (int mt = 0; mt < 4; mt++) {
#pragma unroll
        for (int nt = 0; nt < 4; nt++) {
            long r = r0 + mt * 16;
            int c = bn + cq0 + (nt & 1) * 8 + (nt >> 1) * 64;
            if constexpr (sizeof(OutT) == 2) {
                *(u32*)((char*)C + (r * N + c) * 2) =
                    pack_h2(acc[mt][nt][0], acc[mt][nt][1]);
                *(u32*)((char*)C + ((r + 8) * N + c) * 2) =
                    pack_h2(acc[mt][nt][2], acc[mt][nt][3]);
            } else {
                *(float2*)((float*)C + r * N + c) =
                    make_float2(acc[mt][nt][0], acc[mt][nt][1]);
                *(float2*)((float*)C + (r + 8) * N + c) =
                    make_float2(acc[mt][nt][2], acc[mt][nt][3]);
            }
        }
    }
}

// ===========================================================================
// fp16 tensor-core causal flash attention. BQ=128, BKV=64, D=128, 256 thr.
// ===========================================================================
#define FROWB 272
#define FQ_BYTES (128 * FROWB)
#define FKV_BYTES (64 * FROWB)
#define FSTG (2 * FKV_BYTES)
#define FLASH_SMEM (FQ_BYTES + 2 * FSTG)       // 104448

__global__ __launch_bounds__(256) void flash_h() {
    extern __shared__ char smf[];
    u32 sbase = smem_u32(smf);
    int tid = threadIdx.x;
    int lane = tid & 31, wid = tid >> 5;
    int h = blockIdx.y;
    int qt = 15 - blockIdx.x;                  // big tiles first
    int q0 = qt * 128;
    int nk = 2 * qt + 2;

    u32 smQ = sbase;

#pragma unroll
    for (int i = 0; i < 8; i++) {
        int c = tid + i * 256;
        int r = c >> 4, cb = (c & 15) << 4;
        cp16(smQ + r * FROWB + cb,
             (const char*)(g_Qh + (long)(q0 + r) * HID + h * HD) + cb);
    }
    {
        u32 kb = sbase + FQ_BYTES, vb = kb + FKV_BYTES;
#pragma unroll
        for (int i = 0; i < 4; i++) {
            int c = tid + i * 256;
            int r = c >> 4, cb = (c & 15) << 4;
            long gb = (long)r * HID + h * HD;
            cp16(kb + r * FROWB + cb, (const char*)(g_Kh + gb) + cb);
            cp16(vb + r * FROWB + cb, (const char*)(g_Vh + gb) + cb);
        }
    }
    asm volatile("cp.async.commit_group;\n" ::: "memory");

    u32 aq[8][4];
    float o[16][4];
    float m[2] = {-INFINITY, -INFINITY};
    float l[2] = {0.f, 0.f};
#pragma unroll
    for (int nt = 0; nt < 16; nt++)
#pragma unroll
        for (int q = 0; q < 4; q++) o[nt][q] = 0.f;

    const float SC = 0.1275174461600732f;      // 1/sqrt(128) * log2(e)
    // K (non-trans B): kv rows via lane&7 / lane&16; d chunk via lane&8
    u32 k_off = (u32)(((lane & 7) + ((lane & 16) ? 8 : 0)) * FROWB +
                      ((lane & 8) ? 16 : 0));
    // V (trans B): kv rows via lane&7 / lane&8; d chunk via lane&16
    u32 v_off = (u32)(((lane & 7) + ((lane & 8) ? 8 : 0)) * FROWB +
                      ((lane & 16) ? 16 : 0));
    u32 q_off = (u32)((wid * 16 + (lane & 15)) * FROWB + (lane >> 4) * 16);

    for (int kt = 0; kt < nk; kt++) {
        int k0 = kt * 64;
        asm volatile("cp.async.wait_group 0;\n" ::: "memory");
        __syncthreads();

        if (kt == 0) {
#pragma unroll
            for (int d8 = 0; d8 < 8; d8++)
                ldmx4(smQ + q_off + d8 * 32,
                      aq[d8][0], aq[d8][1], aq[d8][2], aq[d8][3]);
        }
        if (kt + 1 < nk) {
            u32 kb = sbase + FQ_BYTES + ((kt + 1) & 1) * FSTG;
            u32 vb = kb + FKV_BYTES;
            long krow = (long)(kt + 1) * 64;
#pragma unroll
            for (int i = 0; i < 4; i++) {
                int c = tid + i * 256;
                int r = c >> 4, cb = (c & 15) << 4;
                long gb = (krow + r) * HID + h * HD;
                cp16(kb + r * FROWB + cb, (const char*)(g_Kh + gb) + cb);
                cp16(vb + r * FROWB + cb, (const char*)(g_Vh + gb) + cb);
            }
            asm volatile("cp.async.commit_group;\n" ::: "memory");
        }

        u32 kbase = sbase + FQ_BYTES + (kt & 1) * FSTG;
        u32 vbase = kbase + FKV_BYTES;

        // ---- scores: 16 q rows x 64 kv cols -> c[0..7] (8 n-tiles of 8) ----
        float c[8][4];
#pragma unroll
        for (int j = 0; j < 8; j++)
#pragma unroll
            for (int q = 0; q < 4; q++) c[j][q] = 0.f;

#pragma unroll
        for (int d8 = 0; d8 < 8; d8++) {
            u32 bf[4][4];
#pragma unroll
            for (int np = 0; np < 4; np++)      // 4 groups of 16 kv rows = 64
                ldmx4(kbase + k_off + np * (16 * FROWB) + d8 * 32,
                      bf[np][0], bf[np][1], bf[np][2], bf[np][3]);
#pragma unroll
            for (int np = 0; np < 4; np++) {
                mma_h(c[2 * np],     aq[d8], &bf[np][0]);
                mma_h(c[2 * np + 1], aq[d8], &bf[np][2]);
            }
        }

#pragma unroll
        for (int j = 0; j < 8; j++)
#pragma unroll
            for (int q = 0; q < 4; q++) c[j][q] *= SC;

        if (k0 + 63 > q0 + wid * 16) {
            int rbase = q0 + wid * 16 + (lane >> 2);
#pragma unroll
            for (int j = 0; j < 8; j++) {
                int col = k0 + j * 8 + (lane & 3) * 2;
#pragma unroll
                for (int t = 0; t < 2; t++) {
                    int row = rbase + t * 8;
                    if (col > row)     c[j][2 * t]     = -INFINITY;
                    if (col + 1 > row) c[j][2 * t + 1] = -INFINITY;
                }
            }
        }

#pragma unroll
        for (int t = 0; t < 2; t++) {
            float mx = -INFINITY;
#pragma unroll
            for (int j = 0; j < 8; j++)
                mx = fmaxf(mx, fmaxf(c[j][2 * t], c[j][2 * t + 1]));
            mx = fmaxf(mx, __shfl_xor_sync(0xffffffffu, mx, 1));
            mx = fmaxf(mx, __shfl_xor_sync(0xffffffffu, mx, 2));
            float mnew = fmaxf(m[t], mx);
            float corr = exp2f(m[t] - mnew);
            float rs = 0.f;
#pragma unroll
            for (int j = 0; j < 8; j++) {
                float p0 = exp2f(c[j][2 * t] - mnew);
                float p1 = exp2f(c[j][2 * t + 1] - mnew);
                c[j][2 * t] = p0;
                c[j][2 * t + 1] = p1;
                rs += p0 + p1;
            }
            rs += __shfl_xor_sync(0xffffffffu, rs, 1);
            rs += __shfl_xor_sync(0xffffffffu, rs, 2);
            l[t] = l[t] * corr + rs;
            m[t] = mnew;
#pragma unroll
            for (int nt = 0; nt < 16; nt++) {
                o[nt][2 * t] *= corr;
                o[nt][2 * t + 1] *= corr;
            }
        }

        // P fragments: 4 A-frags over kv chunks of 16
        u32 ph[4][4];
#pragma unroll
        for (int t = 0; t < 4; t++) {
            ph[t][0] = pack_h2(c[2 * t][0], c[2 * t][1]);
            ph[t][1] = pack_h2(c[2 * t][2], c[2 * t][3]);
            ph[t][2] = pack_h2(c[2 * t + 1][0], c[2 * t + 1][1]);
            ph[t][3] = pack_h2(c[2 * t + 1][2], c[2 * t + 1][3]);
        }

        // ---- O += P V ----
#pragma unroll
        for (int t = 0; t < 4; t++) {
            u32 vrow = vbase + v_off + t * (16 * FROWB);
#pragma unroll
            for (int np = 0; np < 8; np++) {
                u32 b0, b1, b2, b3;
                ldmx4t(vrow + np * 32, b0, b1, b2, b3);
                u32 bl[2] = {b0, b1};
                u32 bh[2] = {b2, b3};
                mma_h(o[2 * np], ph[t], bl);
                mma_h(o[2 * np + 1], ph[t], bh);
            }
        }
    }

    float inv0 = 1.0f / l[0], inv1 = 1.0f / l[1];
    long row = q0 + wid * 16 + (lane >> 2);
    int colb = h * HD + (lane & 3) * 2;
#pragma unroll
    for (int nt = 0; nt < 16; nt++) {
        int c = colb + nt * 8;
        *(u32*)((char*)g_Ah + (row * HID + c) * 2) =
            pack_h2(o[nt][0] * inv0, o[nt][1] * inv0);
        *(u32*)((char*)g_Ah + ((row + 8) * HID + c) * 2) =
            pack_h2(o[nt][2] * inv1, o[nt][3] * inv1);
    }
}

// ---------------------------------------------------------------------------
extern "C" void kernel_launch(void* const* d_in, const int* in_sizes, int n_in,
                              void* d_out, int out_size) {
    (void)in_sizes; (void)n_in; (void)out_size;
    const float* x   = (const float*)d_in[0];
    const int*   pos = (const int*)d_in[1];
    const float* wq  = (const float*)d_in[2];
    const float* wk  = (const float*)d_in[3];
    const float* wv  = (const float*)d_in[4];
    const float* wo  = (const float*)d_in[5];
    float* out = (float*)d_out;

    __half *Xh, *Wq, *Wk, *Wv, *Wo, *Qh, *Kh, *Vh, *Ah;
    cudaGetSymbolAddress((void**)&Xh, g_Xh);
    cudaGetSymbolAddress((void**)&Wq, g_Wq);
    cudaGetSymbolAddress((void**)&Wk, g_Wk);
    cudaGetSymbolAddress((void**)&Wv, g_Wv);
    cudaGetSymbolAddress((void**)&Wo, g_Wo);
    cudaGetSymbolAddress((void**)&Qh, g_Qh);
    cudaGetSymbolAddress((void**)&Kh, g_Kh);
    cudaGetSymbolAddress((void**)&Vh, g_Vh);
    cudaGetSymbolAddress((void**)&Ah, g_Ah);

    {
        int nx4 = SEQ * HID / 4;
        int nw4 = HID * HID / 4;
        cvt_f2h<<<(nx4 + 255) / 256, 256>>>((const float4*)x, (__half2*)Xh, nx4);
        cvt_f2h<<<(nw4 + 255) / 256, 256>>>((const float4*)wq, (__half2*)Wq, nw4);
        cvt_f2h<<<(nw4 + 255) / 256, 256>>>((const float4*)wk, (__half2*)Wk, nw4);
        cvt_f2h<<<(nw4 + 255) / 256, 256>>>((const float4*)wv, (__half2*)Wv, nw4);
        cvt_f2h<<<(nw4 + 255) / 256, 256>>>((const float4*)wo, (__half2*)Wo, nw4);
    }

    cudaFuncSetAttribute((gemm_h<__half, 1>),
                         cudaFuncAttributeMaxDynamicSharedMemorySize, GEMM_SMEM);
    cudaFuncSetAttribute((gemm_h<__half, 0>),
                         cudaFuncAttributeMaxDynamicSharedMemorySize, GEMM_SMEM);
    cudaFuncSetAttribute((gemm_h<float, 0>),
                         cudaFuncAttributeMaxDynamicSharedMemorySize, GEMM_SMEM);
    cudaFuncSetAttribute(flash_h,
                         cudaFuncAttributeMaxDynamicSharedMemorySize, FLASH_SMEM);

    dim3 gg(HID / 128, SEQ / 128);  // (32, 16)
    gemm_h<__half, 1><<<gg, 256, GEMM_SMEM>>>(Xh, Wq, Qh, pos, SEQ, HID, HID);
    gemm_h<__half, 1><<<gg, 256, GEMM_SMEM>>>(Xh, Wk, Kh, pos, SEQ, HID, HID);
    gemm_h<__half, 0><<<gg, 256, GEMM_SMEM>>>(Xh, Wv, Vh, pos, SEQ, HID, HID);

    flash_h<<<dim3(16, 32), 256, FLASH_SMEM>>>();

    gemm_h<float, 0><<<gg, 256, GEMM_SMEM>>>(Ah, Wo, out, pos, SEQ, HID, HID);
}

// round 7
// speedup vs baseline: 8.8841x; 1.0905x over previous
#include <cuda_runtime.h>
#include <cuda_fp16.h>
#include <math.h>

#define HID 4096
#define SEQ 2048
#define NH 32
#define HD 128

typedef unsigned int u32;

// Static scratch (no cudaMalloc allowed)
__device__ __align__(256) __half g_Xh[SEQ * HID];
__device__ __align__(256) __half g_Wq[HID * HID];
__device__ __align__(256) __half g_Wk[HID * HID];
__device__ __align__(256) __half g_Wv[HID * HID];
__device__ __align__(256) __half g_Wo[HID * HID];
__device__ __align__(256) __half g_Qh[SEQ * HID];
__device__ __align__(256) __half g_Kh[SEQ * HID];
__device__ __align__(256) __half g_Vh[SEQ * HID];
__device__ __align__(256) __half g_Ah[SEQ * HID];

__device__ __forceinline__ u32 smem_u32(const void* p) {
    u32 a;
    asm("{ .reg .u64 t; cvta.to.shared.u64 t, %1; cvt.u32.u64 %0, t; }"
        : "=r"(a) : "l"(p));
    return a;
}
__device__ __forceinline__ void cp16(u32 dst, const void* src) {
    asm volatile("cp.async.cg.shared.global [%0], [%1], 16;\n" :: "r"(dst), "l"(src));
}
__device__ __forceinline__ void ldmx4(u32 addr, u32& r0, u32& r1, u32& r2, u32& r3) {
    asm volatile("ldmatrix.sync.aligned.m8n8.x4.shared.b16 {%0,%1,%2,%3}, [%4];"
                 : "=r"(r0), "=r"(r1), "=r"(r2), "=r"(r3) : "r"(addr));
}
__device__ __forceinline__ void ldmx4t(u32 addr, u32& r0, u32& r1, u32& r2, u32& r3) {
    asm volatile("ldmatrix.sync.aligned.m8n8.x4.trans.shared.b16 {%0,%1,%2,%3}, [%4];"
                 : "=r"(r0), "=r"(r1), "=r"(r2), "=r"(r3) : "r"(addr));
}
__device__ __forceinline__ void mma_h(float* c, const u32* a, const u32* b) {
    asm volatile(
        "mma.sync.aligned.m16n8k16.row.col.f32.f16.f16.f32 "
        "{%0,%1,%2,%3}, {%4,%5,%6,%7}, {%8,%9}, {%0,%1,%2,%3};"
        : "+f"(c[0]), "+f"(c[1]), "+f"(c[2]), "+f"(c[3])
        : "r"(a[0]), "r"(a[1]), "r"(a[2]), "r"(a[3]), "r"(b[0]), "r"(b[1]));
}
__device__ __forceinline__ u32 pack_h2(float a, float b) {
    __half2 h = __floats2half2_rn(a, b);
    return *reinterpret_cast<u32*>(&h);
}

// ---------------------------------------------------------------------------
// fp32 -> fp16: 2 float4 loads + 2 uint2 (8B) stores per thread.
// ---------------------------------------------------------------------------
__global__ void cvt_f2h(const float4* __restrict__ src, uint2* __restrict__ dst,
                        int n4) {
    int i = (blockIdx.x * blockDim.x + threadIdx.x) * 2;
    if (i < n4) {
        float4 v = src[i];
        uint2 o;
        o.x = pack_h2(v.x, v.y);
        o.y = pack_h2(v.z, v.w);
        dst[i] = o;
        if (i + 1 < n4) {
            float4 w = src[i + 1];
            uint2 p;
            p.x = pack_h2(w.x, w.y);
            p.y = pack_h2(w.z, w.w);
            dst[i + 1] = p;
        }
    }
}

// ===========================================================================
// fp16 mma GEMM (NT): C[M,N] = A[M,K]h * B[N,K]h^T, fp32 accumulate.
// BM=BN=128, BK=64. 256 threads = 8 warps (2 x 4), warp tile 64x32.
// Warp's 32 cols = two 16-col chunks at n and n+64 (RoPE pairs local).
// ===========================================================================
#define ROWB 144
#define GTILE (128 * ROWB)
#define GSTG  (2 * GTILE)
#define GEMM_SMEM (2 * GSTG)                  // 73728

__device__ __forceinline__ void gemm_stage_load(
    const __half* __restrict__ A, const __half* __restrict__ Bw, int K,
    int bm, int bn, int k0, u32 sA, u32 sB, int tid)
{
#pragma unroll
    for (int i = 0; i < 4; i++) {
        int c = tid + i * 256;
        int r = c >> 3, cb = (c & 7) << 4;
        cp16(sA + r * ROWB + cb,
             (const char*)(A + (long)(bm + r) * K + k0) + cb);
    }
#pragma unroll
    for (int i = 0; i < 4; i++) {
        int c = tid + i * 256;
        int r = c >> 3, cb = (c & 7) << 4;
        cp16(sB + r * ROWB + cb,
             (const char*)(Bw + (long)(bn + r) * K + k0) + cb);
    }
}

// Core mainloop shared by both GEMM kernels.
__device__ __forceinline__ void gemm_core(
    const __half* __restrict__ A, const __half* __restrict__ Bw,
    int bm, int bn, int K, u32 sbase, int tid, int lane,
    u32 a_off, u32 b_off, float acc[4][4][4])
{
    const int KT = K / 64;
    u32 stA[2] = {sbase, sbase + GSTG};
    u32 stB[2] = {sbase + GTILE, sbase + GSTG + GTILE};

    gemm_stage_load(A, Bw, K, bm, bn, 0, stA[0], stB[0], tid);
    asm volatile("cp.async.commit_group;\n" ::: "memory");

    for (int kt = 0; kt < KT; kt++) {
        int slot = kt & 1;
        asm volatile("cp.async.wait_group 0;\n" ::: "memory");
        __syncthreads();
        if (kt + 1 < KT) {
            gemm_stage_load(A, Bw, K, bm, bn, (kt + 1) * 64,
                            stA[slot ^ 1], stB[slot ^ 1], tid);
            asm volatile("cp.async.commit_group;\n" ::: "memory");
        }

        u32 aB = stA[slot] + a_off;
        u32 bB = stB[slot] + b_off;
#pragma unroll
        for (int ks = 0; ks < 4; ks++) {
            u32 af[4][4], bf[2][4];
#pragma unroll
            for (int mt = 0; mt < 4; mt++)
                ldmx4(aB + mt * (16 * ROWB) + ks * 32,
                      af[mt][0], af[mt][1], af[mt][2], af[mt][3]);
#pragma unroll
            for (int np = 0; np < 2; np++)
                ldmx4(bB + np * (64 * ROWB) + ks * 32,
                      bf[np][0], bf[np][1], bf[np][2], bf[np][3]);
#pragma unroll
            for (int mt = 0; mt < 4; mt++)
#pragma unroll
                for (int nt = 0; nt < 4; nt++)
                    mma_h(acc[mt][nt], af[mt], &bf[nt >> 1][(nt & 1) * 2]);
        }
        __syncthreads();
    }
}

// Fused Q/K/V projection: blockIdx.z selects weight/output; z<2 applies RoPE.
__global__ __launch_bounds__(256, 2) void gemm_qkv(const __half* __restrict__ A,
                                                   const int* __restrict__ pos) {
    extern __shared__ char smg[];
    u32 sbase = smem_u32(smg);
    int tid = threadIdx.x;
    int lane = tid & 31, wid = tid >> 5;
    int wm = wid & 1, wn = wid >> 1;
    int bm = blockIdx.y * 128;
    int bn = blockIdx.x * 128;
    int z = blockIdx.z;

    const __half* Bw = (z == 0) ? g_Wq : (z == 1) ? g_Wk : g_Wv;
    __half* C = (z == 0) ? g_Qh : (z == 1) ? g_Kh : g_Vh;

    u32 a_off = (u32)((wm * 64 + (lane & 15)) * ROWB + (lane >> 4) * 16);
    u32 b_off = (u32)((wn * 16 + (lane & 7) + ((lane & 16) ? 8 : 0)) * ROWB +
                      ((lane & 8) ? 16 : 0));

    float acc[4][4][4];
#pragma unroll
    for (int i = 0; i < 4; i++)
#pragma unroll
        for (int j = 0; j < 4; j++)
#pragma unroll
            for (int q = 0; q < 4; q++) acc[i][j][q] = 0.f;

    gemm_core(A, Bw, bm, bn, HID, sbase, tid, lane, a_off, b_off, acc);

    int r0 = bm + wm * 64 + (lane >> 2);
    int cq0 = wn * 16 + (lane & 3) * 2;

    if (z < 2) {
        int rh = NH - 1 - blockIdx.x;            // reversed head order
        float ratio_inv = 1.0f / (1.0f + 2.0f * ((float)rh / (float)NH));
        const float L2 = 13.287712379549449f;    // log2(10000)
#pragma unroll
        for (int mt = 0; mt < 4; mt++) {
#pragma unroll
            for (int t = 0; t < 2; t++) {
                int row = r0 + mt * 16 + t * 8;
                float tp = (float)pos[row] * ratio_inv;
#pragma unroll
                for (int loc = 0; loc < 2; loc++) {
#pragma unroll
                    for (int cq = 0; cq < 2; cq++) {
                        int d = cq0 + loc * 8 + cq;
                        float inv_freq = exp2f(-((float)d * (1.0f / 64.0f)) * L2);
                        float sn, cs;
                        sincosf(tp * inv_freq, &sn, &cs);
                        int q = t * 2 + cq;
                        float a = acc[mt][loc][q];
                        float b = acc[mt][loc + 2][q];
                        acc[mt][loc][q]     = a * cs - b * sn;
                        acc[mt][loc + 2][q] = b * cs + a * sn;
                    }
                }
            }
        }
    }

#pragma unroll
    for (int mt = 0; mt < 4; mt++) {
#pragma unroll
        for (int nt = 0; nt < 4; nt++) {
            long r = r0 + mt * 16;
            int c = bn + cq0 + (nt & 1) * 8 + (nt >> 1) * 64;
            *(u32*)((char*)C + (r * HID + c) * 2) =
                pack_h2(acc[mt][nt][0], acc[mt][nt][1]);
            *(u32*)((char*)C + ((r + 8) * HID + c) * 2) =
                pack_h2(acc[mt][nt][2], acc[mt][nt][3]);
        }
    }
}

// Output projection: fp32 out.
__global__ __launch_bounds__(256, 2) void gemm_o(const __half* __restrict__ A,
                                                 float* __restrict__ C) {
    extern __shared__ char smg[];
    u32 sbase = smem_u32(smg);
    int tid = threadIdx.x;
    int lane = tid & 31, wid = tid >> 5;
    int wm = wid & 1, wn = wid >> 1;
    int bm = blockIdx.y * 128;
    int bn = blockIdx.x * 128;

    u32 a_off = (u32)((wm * 64 + (lane & 15)) * ROWB + (lane >> 4) * 16);
    u32 b_off = (u32)((wn * 16 + (lane & 7) + ((lane & 16) ? 8 : 0)) * ROWB +
                      ((lane & 8) ? 16 : 0));

    float acc[4][4][4];
#pragma unroll
    for (int i = 0; i < 4; i++)
#pragma unroll
        for (int j = 0; j < 4; j++)
#pragma unroll
            for (int q = 0; q < 4; q++) acc[i][j][q] = 0.f;

    gemm_core(A, g_Wo, bm, bn, HID, sbase, tid, lane, a_off, b_off, acc);

    int r0 = bm + wm * 64 + (lane >> 2);
    int cq0 = wn * 16 + (lane & 3) * 2;
#pragma unroll
    for (int mt = 0; mt < 4; mt++) {
#pragma unroll
        for (int nt = 0; nt < 4; nt++) {
            long r = r0 + mt * 16;
            int c = bn + cq0 + (nt & 1) * 8 + (nt >> 1) * 64;
            *(float2*)&C[r * HID + c] =
                make_float2(acc[mt][nt][0], acc[mt][nt][1]);
            *(float2*)&C[(r + 8) * HID + c] =
                make_float2(acc[mt][nt][2], acc[mt][nt][3]);
        }
    }
}

// ===========================================================================
// fp16 tensor-core causal flash attention. BQ=64, BKV=64, D=128, 128 thr.
// Smaller CTA -> 2 CTAs/SM (regs + 87KB smem) so softmax hides behind MMA.
// ===========================================================================
#define FROWB 272
#define FTILE (64 * FROWB)                     // 17408
#define FSTG (2 * FTILE)                       // K + V per stage
#define FLASH_SMEM (FTILE + 2 * FSTG)          // 87040

__global__ __launch_bounds__(128) void flash_h() {
    extern __shared__ char smf[];
    u32 sbase = smem_u32(smf);
    int tid = threadIdx.x;
    int lane = tid & 31, wid = tid >> 5;       // 4 warps
    int h = blockIdx.y;
    int qt = 31 - blockIdx.x;                  // big tiles first
    int q0 = qt * 64;
    int nk = qt + 1;

    u32 smQ = sbase;

    // Q load: 64 rows x 16 chunks = 1024, 128 threads -> 8 iters
#pragma unroll
    for (int i = 0; i < 8; i++) {
        int c = tid + i * 128;
        int r = c >> 4, cb = (c & 15) << 4;
        cp16(smQ + r * FROWB + cb,
             (const char*)(g_Qh + (long)(q0 + r) * HID + h * HD) + cb);
    }
    {
        u32 kb = sbase + FTILE, vb = kb + FTILE;
#pragma unroll
        for (int i = 0; i < 8; i++) {
            int c = tid + i * 128;
            int r = c >> 4, cb = (c & 15) << 4;
            long gb = (long)r * HID + h * HD;
            cp16(kb + r * FROWB + cb, (const char*)(g_Kh + gb) + cb);
            cp16(vb + r * FROWB + cb, (const char*)(g_Vh + gb) + cb);
        }
    }
    asm volatile("cp.async.commit_group;\n" ::: "memory");

    u32 aq[8][4];
    float o[16][4];
    float m[2] = {-INFINITY, -INFINITY};
    float l[2] = {0.f, 0.f};
#pragma unroll
    for (int nt = 0; nt < 16; nt++)
#pragma unroll
        for (int q = 0; q < 4; q++) o[nt][q] = 0.f;

    const float SC = 0.1275174461600732f;      // 1/sqrt(128) * log2(e)
    u32 k_off = (u32)(((lane & 7) + ((lane & 16) ? 8 : 0)) * FROWB +
                      ((lane & 8) ? 16 : 0));
    u32 v_off = (u32)(((lane & 7) + ((lane & 8) ? 8 : 0)) * FROWB +
                      ((lane & 16) ? 16 : 0));
    u32 q_off = (u32)((wid * 16 + (lane & 15)) * FROWB + (lane >> 4) * 16);

    for (int kt = 0; kt < nk; kt++) {
        int k0 = kt * 64;
        asm volatile("cp.async.wait_group 0;\n" ::: "memory");
        __syncthreads();

        if (kt == 0) {
#pragma unroll
            for (int d8 = 0; d8 < 8; d8++)
                ldmx4(smQ + q_off + d8 * 32,
                      aq[d8][0], aq[d8][1], aq[d8][2], aq[d8][3]);
        }
        if (kt + 1 < nk) {
            u32 kb = sbase + FTILE + ((kt + 1) & 1) * FSTG;
            u32 vb = kb + FTILE;
            long krow = (long)(kt + 1) * 64;
#pragma unroll
            for (int i = 0; i < 8; i++) {
                int c = tid + i * 128;
                int r = c >> 4, cb = (c & 15) << 4;
                long gb = (krow + r) * HID + h * HD;
                cp16(kb + r * FROWB + cb, (const char*)(g_Kh + gb) + cb);
                cp16(vb + r * FROWB + cb, (const char*)(g_Vh + gb) + cb);
            }
            asm volatile("cp.async.commit_group;\n" ::: "memory");
        }

        u32 kbase = sbase + FTILE + (kt & 1) * FSTG;
        u32 vbase = kbase + FTILE;

        // ---- scores: 16 q rows x 64 kv cols -> c[0..7] ----
        float c[8][4];
#pragma unroll
        for (int j = 0; j < 8; j++)
#pragma unroll
            for (int q = 0; q < 4; q++) c[j][q] = 0.f;

#pragma unroll
        for (int d8 = 0; d8 < 8; d8++) {
            u32 bf[4][4];
#pragma unroll
            for (int np = 0; np < 4; np++)
                ldmx4(kbase + k_off + np * (16 * FROWB) + d8 * 32,
                      bf[np][0], bf[np][1], bf[np][2], bf[np][3]);
#pragma unroll
            for (int np = 0; np < 4; np++) {
                mma_h(c[2 * np],     aq[d8], &bf[np][0]);
                mma_h(c[2 * np + 1], aq[d8], &bf[np][2]);
            }
        }

#pragma unroll
        for (int j = 0; j < 8; j++)
#pragma unroll
            for (int q = 0; q < 4; q++) c[j][q] *= SC;

        if (k0 + 63 > q0 + wid * 16) {
            int rbase = q0 + wid * 16 + (lane >> 2);
#pragma unroll
            for (int j = 0; j < 8; j++) {
                int col = k0 + j * 8 + (lane & 3) * 2;
#pragma unroll
                for (int t = 0; t < 2; t++) {
                    int row = rbase + t * 8;
                    if (col > row)     c[j][2 * t]     = -INFINITY;
                    if (col + 1 > row) c[j][2 * t + 1] = -INFINITY;
                }
            }
        }

#pragma unroll
        for (int t = 0; t < 2; t++) {
            float mx = -INFINITY;
#pragma unroll
            for (int j = 0; j < 8; j++)
                mx = fmaxf(mx, fmaxf(c[j][2 * t], c[j][2 * t + 1]));
            mx = fmaxf(mx, __shfl_xor_sync(0xffffffffu, mx, 1));
            mx = fmaxf(mx, __shfl_xor_sync(0xffffffffu, mx, 2));
            float mnew = fmaxf(m[t], mx);
            float corr = exp2f(m[t] - mnew);
            float rs = 0.f;
#pragma unroll
            for (int j = 0; j < 8; j++) {
                float p0 = exp2f(c[j][2 * t] - mnew);
                float p1 = exp2f(c[j][2 * t + 1] - mnew);
                c[j][2 * t] = p0;
                c[j][2 * t + 1] = p1;
                rs += p0 + p1;
            }
            rs += __shfl_xor_sync(0xffffffffu, rs, 1);
            rs += __shfl_xor_sync(0xffffffffu, rs, 2);
            l[t] = l[t] * corr + rs;
            m[t] = mnew;
#pragma unroll
            for (int nt = 0; nt < 16; nt++) {
                o[nt][2 * t] *= corr;
                o[nt][2 * t + 1] *= corr;
            }
        }

        u32 ph[4][4];
#pragma unroll
        for (int t = 0; t < 4; t++) {
            ph[t][0] = pack_h2(c[2 * t][0], c[2 * t][1]);
            ph[t][1] = pack_h2(c[2 * t][2], c[2 * t][3]);
            ph[t][2] = pack_h2(c[2 * t + 1][0], c[2 * t + 1][1]);
            ph[t][3] = pack_h2(c[2 * t + 1][2], c[2 * t + 1][3]);
        }

        // ---- O += P V ----
#pragma unroll
        for (int t = 0; t < 4; t++) {
            u32 vrow = vbase + v_off + t * (16 * FROWB);
#pragma unroll
            for (int np = 0; np < 8; np++) {
                u32 b0, b1, b2, b3;
                ldmx4t(vrow + np * 32, b0, b1, b2, b3);
                u32 bl[2] = {b0, b1};
                u32 bh[2] = {b2, b3};
                mma_h(o[2 * np], ph[t], bl);
                mma_h(o[2 * np + 1], ph[t], bh);
            }
        }
    }

    float inv0 = 1.0f / l[0], inv1 = 1.0f / l[1];
    long row = q0 + wid * 16 + (lane >> 2);
    int colb = h * HD + (lane & 3) * 2;
#pragma unroll
    for (int nt = 0; nt < 16; nt++) {
        int c = colb + nt * 8;
        *(u32*)((char*)g_Ah + (row * HID + c) * 2) =
            pack_h2(o[nt][0] * inv0, o[nt][1] * inv0);
        *(u32*)((char*)g_Ah + ((row + 8) * HID + c) * 2) =
            pack_h2(o[nt][2] * inv1, o[nt][3] * inv1);
    }
}

// ---------------------------------------------------------------------------
extern "C" void kernel_launch(void* const* d_in, const int* in_sizes, int n_in,
                              void* d_out, int out_size) {
    (void)in_sizes; (void)n_in; (void)out_size;
    const float* x   = (const float*)d_in[0];
    const int*   pos = (const int*)d_in[1];
    const float* wq  = (const float*)d_in[2];
    const float* wk  = (const float*)d_in[3];
    const float* wv  = (const float*)d_in[4];
    const float* wo  = (const float*)d_in[5];
    float* out = (float*)d_out;

    __half *Xh, *Wq, *Wk, *Wv, *Wo, *Ah;
    cudaGetSymbolAddress((void**)&Xh, g_Xh);
    cudaGetSymbolAddress((void**)&Wq, g_Wq);
    cudaGetSymbolAddress((void**)&Wk, g_Wk);
    cudaGetSymbolAddress((void**)&Wv, g_Wv);
    cudaGetSymbolAddress((void**)&Wo, g_Wo);
    cudaGetSymbolAddress((void**)&Ah, g_Ah);

    {
        int nx4 = SEQ * HID / 4;
        int nw4 = HID * HID / 4;
        int bx = (nx4 / 2 + 255) / 256;
        int bw = (nw4 / 2 + 255) / 256;
        cvt_f2h<<<bx, 256>>>((const float4*)x, (uint2*)Xh, nx4);
        cvt_f2h<<<bw, 256>>>((const float4*)wq, (uint2*)Wq, nw4);
        cvt_f2h<<<bw, 256>>>((const float4*)wk, (uint2*)Wk, nw4);
        cvt_f2h<<<bw, 256>>>((const float4*)wv, (uint2*)Wv, nw4);
        cvt_f2h<<<bw, 256>>>((const float4*)wo, (uint2*)Wo, nw4);
    }

    cudaFuncSetAttribute(gemm_qkv,
                         cudaFuncAttributeMaxDynamicSharedMemorySize, GEMM_SMEM);
    cudaFuncSetAttribute(gemm_o,
                         cudaFuncAttributeMaxDynamicSharedMemorySize, GEMM_SMEM);
    cudaFuncSetAttribute(flash_h,
                         cudaFuncAttributeMaxDynamicSharedMemorySize, FLASH_SMEM);

    gemm_qkv<<<dim3(32, 16, 3), 256, GEMM_SMEM>>>(Xh, pos);

    flash_h<<<dim3(32, 32), 128, FLASH_SMEM>>>();

    gemm_o<<<dim3(32, 16), 256, GEMM_SMEM>>>(Ah, out);
}

// round 8
// speedup vs baseline: 9.0538x; 1.0191x over previous
#include <cuda_runtime.h>
#include <cuda_fp16.h>
#include <math.h>

#define HID 4096
#define SEQ 2048
#define NH 32
#define HD 128

typedef unsigned int u32;

// Static scratch (no cudaMalloc allowed)
__device__ __align__(256) __half g_Xh[SEQ * HID];
__device__ __align__(256) __half g_Wq[HID * HID];
__device__ __align__(256) __half g_Wk[HID * HID];
__device__ __align__(256) __half g_Wv[HID * HID];
__device__ __align__(256) __half g_Wo[HID * HID];
__device__ __align__(256) __half g_Qh[SEQ * HID];
__device__ __align__(256) __half g_Kh[SEQ * HID];
__device__ __align__(256) __half g_Vh[SEQ * HID];
__device__ __align__(256) __half g_Ah[SEQ * HID];

__device__ __forceinline__ u32 smem_u32(const void* p) {
    u32 a;
    asm("{ .reg .u64 t; cvta.to.shared.u64 t, %1; cvt.u32.u64 %0, t; }"
        : "=r"(a) : "l"(p));
    return a;
}
__device__ __forceinline__ void cp16(u32 dst, const void* src) {
    asm volatile("cp.async.cg.shared.global [%0], [%1], 16;\n" :: "r"(dst), "l"(src));
}
__device__ __forceinline__ void ldmx4(u32 addr, u32& r0, u32& r1, u32& r2, u32& r3) {
    asm volatile("ldmatrix.sync.aligned.m8n8.x4.shared.b16 {%0,%1,%2,%3}, [%4];"
                 : "=r"(r0), "=r"(r1), "=r"(r2), "=r"(r3) : "r"(addr));
}
__device__ __forceinline__ void ldmx4t(u32 addr, u32& r0, u32& r1, u32& r2, u32& r3) {
    asm volatile("ldmatrix.sync.aligned.m8n8.x4.trans.shared.b16 {%0,%1,%2,%3}, [%4];"
                 : "=r"(r0), "=r"(r1), "=r"(r2), "=r"(r3) : "r"(addr));
}
__device__ __forceinline__ void mma_h(float* c, const u32* a, const u32* b) {
    asm volatile(
        "mma.sync.aligned.m16n8k16.row.col.f32.f16.f16.f32 "
        "{%0,%1,%2,%3}, {%4,%5,%6,%7}, {%8,%9}, {%0,%1,%2,%3};"
        : "+f"(c[0]), "+f"(c[1]), "+f"(c[2]), "+f"(c[3])
        : "r"(a[0]), "r"(a[1]), "r"(a[2]), "r"(a[3]), "r"(b[0]), "r"(b[1]));
}
__device__ __forceinline__ u32 pack_h2(float a, float b) {
    __half2 h = __floats2half2_rn(a, b);
    return *reinterpret_cast<u32*>(&h);
}

// ---------------------------------------------------------------------------
// fp32 -> fp16 converts. cvt_x: one tensor. cvt_w: all 4 weights (grid.y).
// ---------------------------------------------------------------------------
__device__ __forceinline__ void cvt_body(const float4* __restrict__ src,
                                         uint2* __restrict__ dst, int n4, int i) {
    if (i < n4) {
        float4 v = src[i];
        uint2 o;
        o.x = pack_h2(v.x, v.y);
        o.y = pack_h2(v.z, v.w);
        dst[i] = o;
        if (i + 1 < n4) {
            float4 w = src[i + 1];
            uint2 p;
            p.x = pack_h2(w.x, w.y);
            p.y = pack_h2(w.z, w.w);
            dst[i + 1] = p;
        }
    }
}

__global__ void cvt_x(const float4* __restrict__ src, uint2* __restrict__ dst,
                      int n4) {
    int i = (blockIdx.x * blockDim.x + threadIdx.x) * 2;
    cvt_body(src, dst, n4, i);
}

__global__ void cvt_w(const float4* __restrict__ s0, const float4* __restrict__ s1,
                      const float4* __restrict__ s2, const float4* __restrict__ s3,
                      int n4) {
    int z = blockIdx.y;
    const float4* src = (z == 0) ? s0 : (z == 1) ? s1 : (z == 2) ? s2 : s3;
    uint2* dst = (z == 0) ? (uint2*)g_Wq : (z == 1) ? (uint2*)g_Wk
               : (z == 2) ? (uint2*)g_Wv : (uint2*)g_Wo;
    int i = (blockIdx.x * blockDim.x + threadIdx.x) * 2;
    cvt_body(src, dst, n4, i);
}

// ===========================================================================
// fp16 mma GEMM (NT): C[M,N] = A[M,K]h * B[N,K]h^T, fp32 accumulate.
// BM=BN=128, BK=64. 256 threads = 8 warps (2 x 4), warp tile 64x32.
// Warp's 32 cols = two 16-col chunks at n and n+64 (RoPE pairs local).
// 3-stage cp.async ring: ONE __syncthreads per K-iter (slot reuse distance 2).
// ===========================================================================
#define ROWB 144
#define GTILE (128 * ROWB)
#define GSTG  (2 * GTILE)                     // 36864 per stage
#define GEMM_SMEM (3 * GSTG)                  // 110592 (x2 CTAs = 216KB)

__device__ __forceinline__ void gemm_stage_load(
    const __half* __restrict__ A, const __half* __restrict__ Bw, int K,
    int bm, int bn, int k0, u32 sA, u32 sB, int tid)
{
#pragma unroll
    for (int i = 0; i < 4; i++) {
        int c = tid + i * 256;
        int r = c >> 3, cb = (c & 7) << 4;
        cp16(sA + r * ROWB + cb,
             (const char*)(A + (long)(bm + r) * K + k0) + cb);
    }
#pragma unroll
    for (int i = 0; i < 4; i++) {
        int c = tid + i * 256;
        int r = c >> 3, cb = (c & 7) << 4;
        cp16(sB + r * ROWB + cb,
             (const char*)(Bw + (long)(bn + r) * K + k0) + cb);
    }
}

__device__ __forceinline__ void gemm_core(
    const __half* __restrict__ A, const __half* __restrict__ Bw,
    int bm, int bn, int K, u32 sbase, int tid,
    u32 a_off, u32 b_off, float acc[4][4][4])
{
    const int KT = K / 64;

    // prologue: stages 0 and 1
    gemm_stage_load(A, Bw, K, bm, bn, 0, sbase, sbase + GTILE, tid);
    asm volatile("cp.async.commit_group;\n" ::: "memory");
    gemm_stage_load(A, Bw, K, bm, bn, 64, sbase + GSTG, sbase + GSTG + GTILE, tid);
    asm volatile("cp.async.commit_group;\n" ::: "memory");

    int slot = 0;
    for (int kt = 0; kt < KT; kt++) {
        asm volatile("cp.async.wait_group %0;\n" :: "n"(1) : "memory");
        __syncthreads();

        if (kt + 2 < KT) {
            int ps = slot + 2;
            if (ps >= 3) ps -= 3;
            u32 st = sbase + ps * GSTG;
            gemm_stage_load(A, Bw, K, bm, bn, (kt + 2) * 64, st, st + GTILE, tid);
        }
        asm volatile("cp.async.commit_group;\n" ::: "memory");

        u32 aB = sbase + slot * GSTG + a_off;
        u32 bB = sbase + slot * GSTG + GTILE + b_off;
#pragma unroll
        for (int ks = 0; ks < 4; ks++) {
            u32 af[4][4], bf[2][4];
#pragma unroll
            for (int mt = 0; mt < 4; mt++)
                ldmx4(aB + mt * (16 * ROWB) + ks * 32,
                      af[mt][0], af[mt][1], af[mt][2], af[mt][3]);
#pragma unroll
            for (int np = 0; np < 2; np++)
                ldmx4(bB + np * (64 * ROWB) + ks * 32,
                      bf[np][0], bf[np][1], bf[np][2], bf[np][3]);
#pragma unroll
            for (int mt = 0; mt < 4; mt++)
#pragma unroll
                for (int nt = 0; nt < 4; nt++)
                    mma_h(acc[mt][nt], af[mt], &bf[nt >> 1][(nt & 1) * 2]);
        }
        if (++slot == 3) slot = 0;
    }
}

// Fused Q/K/V projection: blockIdx.z selects weight/output; z<2 applies RoPE.
__global__ __launch_bounds__(256, 2) void gemm_qkv(const __half* __restrict__ A,
                                                   const int* __restrict__ pos) {
    extern __shared__ char smg[];
    u32 sbase = smem_u32(smg);
    int tid = threadIdx.x;
    int lane = tid & 31, wid = tid >> 5;
    int wm = wid & 1, wn = wid >> 1;
    int bm = blockIdx.y * 128;
    int bn = blockIdx.x * 128;
    int z = blockIdx.z;

    const __half* Bw = (z == 0) ? g_Wq : (z == 1) ? g_Wk : g_Wv;
    __half* C = (z == 0) ? g_Qh : (z == 1) ? g_Kh : g_Vh;

    u32 a_off = (u32)((wm * 64 + (lane & 15)) * ROWB + (lane >> 4) * 16);
    u32 b_off = (u32)((wn * 16 + (lane & 7) + ((lane & 16) ? 8 : 0)) * ROWB +
                      ((lane & 8) ? 16 : 0));

    float acc[4][4][4];
#pragma unroll
    for (int i = 0; i < 4; i++)
#pragma unroll
        for (int j = 0; j < 4; j++)
#pragma unroll
            for (int q = 0; q < 4; q++) acc[i][j][q] = 0.f;

    gemm_core(A, Bw, bm, bn, HID, sbase, tid, a_off, b_off, acc);

    int r0 = bm + wm * 64 + (lane >> 2);
    int cq0 = wn * 16 + (lane & 3) * 2;

    if (z < 2) {
        int rh = NH - 1 - blockIdx.x;            // reversed head order
        float ratio_inv = 1.0f / (1.0f + 2.0f * ((float)rh / (float)NH));
        const float L2 = 13.287712379549449f;    // log2(10000)
#pragma unroll
        for (int mt = 0; mt < 4; mt++) {
#pragma unroll
            for (int t = 0; t < 2; t++) {
                int row = r0 + mt * 16 + t * 8;
                float tp = (float)pos[row] * ratio_inv;
#pragma unroll
                for (int loc = 0; loc < 2; loc++) {
#pragma unroll
                    for (int cq = 0; cq < 2; cq++) {
                        int d = cq0 + loc * 8 + cq;
                        float inv_freq = exp2f(-((float)d * (1.0f / 64.0f)) * L2);
                        float sn, cs;
                        sincosf(tp * inv_freq, &sn, &cs);
                        int q = t * 2 + cq;
                        float a = acc[mt][loc][q];
                        float b = acc[mt][loc + 2][q];
                        acc[mt][loc][q]     = a * cs - b * sn;
                        acc[mt][loc + 2][q] = b * cs + a * sn;
                    }
                }
            }
        }
    }

#pragma unroll
    for (int mt = 0; mt < 4; mt++) {
#pragma unroll
        for (int nt = 0; nt < 4; nt++) {
            long r = r0 + mt * 16;
            int c = bn + cq0 + (nt & 1) * 8 + (nt >> 1) * 64;
            *(u32*)((char*)C + (r * HID + c) * 2) =
                pack_h2(acc[mt][nt][0], acc[mt][nt][1]);
            *(u32*)((char*)C + ((r + 8) * HID + c) * 2) =
                pack_h2(acc[mt][nt][2], acc[mt][nt][3]);
        }
    }
}

// Output projection: fp32 out.
__global__ __launch_bounds__(256, 2) void gemm_o(const __half* __restrict__ A,
                                                 float* __restrict__ C) {
    extern __shared__ char smg[];
    u32 sbase = smem_u32(smg);
    int tid = threadIdx.x;
    int lane = tid & 31, wid = tid >> 5;
    int wm = wid & 1, wn = wid >> 1;
    int bm = blockIdx.y * 128;
    int bn = blockIdx.x * 128;

    u32 a_off = (u32)((wm * 64 + (lane & 15)) * ROWB + (lane >> 4) * 16);
    u32 b_off = (u32)((wn * 16 + (lane & 7) + ((lane & 16) ? 8 : 0)) * ROWB +
                      ((lane & 8) ? 16 : 0));

    float acc[4][4][4];
#pragma unroll
    for (int i = 0; i < 4; i++)
#pragma unroll
        for (int j = 0; j < 4; j++)
#pragma unroll
            for (int q = 0; q < 4; q++) acc[i][j][q] = 0.f;

    gemm_core(A, g_Wo, bm, bn, HID, sbase, tid, a_off, b_off, acc);

    int r0 = bm + wm * 64 + (lane >> 2);
    int cq0 = wn * 16 + (lane & 3) * 2;
#pragma unroll
    for (int mt = 0; mt < 4; mt++) {
#pragma unroll
        for (int nt = 0; nt < 4; nt++) {
            long r = r0 + mt * 16;
            int c = bn + cq0 + (nt & 1) * 8 + (nt >> 1) * 64;
            *(float2*)&C[r * HID + c] =
                make_float2(acc[mt][nt][0], acc[mt][nt][1]);
            *(float2*)&C[(r + 8) * HID + c] =
                make_float2(acc[mt][nt][2], acc[mt][nt][3]);
        }
    }
}

// ===========================================================================
// fp16 tensor-core causal flash attention. BQ=64, BKV=64, D=128, 128 thr.
// 2 CTAs/SM so softmax of one CTA hides behind MMA of the other.
// ===========================================================================
#define FROWB 272
#define FTILE (64 * FROWB)                     // 17408
#define FSTG (2 * FTILE)                       // K + V per stage
#define FLASH_SMEM (FTILE + 2 * FSTG)          // 87040

__global__ __launch_bounds__(128, 2) void flash_h() {
    extern __shared__ char smf[];
    u32 sbase = smem_u32(smf);
    int tid = threadIdx.x;
    int lane = tid & 31, wid = tid >> 5;       // 4 warps
    int h = blockIdx.y;
    int qt = 31 - blockIdx.x;                  // big tiles first
    int q0 = qt * 64;
    int nk = qt + 1;

    u32 smQ = sbase;

#pragma unroll
    for (int i = 0; i < 8; i++) {
        int c = tid + i * 128;
        int r = c >> 4, cb = (c & 15) << 4;
        cp16(smQ + r * FROWB + cb,
             (const char*)(g_Qh + (long)(q0 + r) * HID + h * HD) + cb);
    }
    {
        u32 kb = sbase + FTILE, vb = kb + FTILE;
#pragma unroll
        for (int i = 0; i < 8; i++) {
            int c = tid + i * 128;
            int r = c >> 4, cb = (c & 15) << 4;
            long gb = (long)r * HID + h * HD;
            cp16(kb + r * FROWB + cb, (const char*)(g_Kh + gb) + cb);
            cp16(vb + r * FROWB + cb, (const char*)(g_Vh + gb) + cb);
        }
    }
    asm volatile("cp.async.commit_group;\n" ::: "memory");

    u32 aq[8][4];
    float o[16][4];
    float m[2] = {-INFINITY, -INFINITY};
    float l[2] = {0.f, 0.f};
#pragma unroll
    for (int nt = 0; nt < 16; nt++)
#pragma unroll
        for (int q = 0; q < 4; q++) o[nt][q] = 0.f;

    const float SC = 0.1275174461600732f;      // 1/sqrt(128) * log2(e)
    u32 k_off = (u32)(((lane & 7) + ((lane & 16) ? 8 : 0)) * FROWB +
                      ((lane & 8) ? 16 : 0));
    u32 v_off = (u32)(((lane & 7) + ((lane & 8) ? 8 : 0)) * FROWB +
                      ((lane & 16) ? 16 : 0));
    u32 q_off = (u32)((wid * 16 + (lane & 15)) * FROWB + (lane >> 4) * 16);

    for (int kt = 0; kt < nk; kt++) {
        int k0 = kt * 64;
        asm volatile("cp.async.wait_group 0;\n" ::: "memory");
        __syncthreads();

        if (kt == 0) {
#pragma unroll
            for (int d8 = 0; d8 < 8; d8++)
                ldmx4(smQ + q_off + d8 * 32,
                      aq[d8][0], aq[d8][1], aq[d8][2], aq[d8][3]);
        }
        if (kt + 1 < nk) {
            u32 kb = sbase + FTILE + ((kt + 1) & 1) * FSTG;
            u32 vb = kb + FTILE;
            long krow = (long)(kt + 1) * 64;
#pragma unroll
            for (int i = 0; i < 8; i++) {
                int c = tid + i * 128;
                int r = c >> 4, cb = (c & 15) << 4;
                long gb = (krow + r) * HID + h * HD;
                cp16(kb + r * FROWB + cb, (const char*)(g_Kh + gb) + cb);
                cp16(vb + r * FROWB + cb, (const char*)(g_Vh + gb) + cb);
            }
            asm volatile("cp.async.commit_group;\n" ::: "memory");
        }

        u32 kbase = sbase + FTILE + (kt & 1) * FSTG;
        u32 vbase = kbase + FTILE;

        float c[8][4];
#pragma unroll
        for (int j = 0; j < 8; j++)
#pragma unroll
            for (int q = 0; q < 4; q++) c[j][q] = 0.f;

#pragma unroll
        for (int d8 = 0; d8 < 8; d8++) {
            u32 bf[4][4];
#pragma unroll
            for (int np = 0; np < 4; np++)
                ldmx4(kbase + k_off + np * (16 * FROWB) + d8 * 32,
                      bf[np][0], bf[np][1], bf[np][2], bf[np][3]);
#pragma unroll
            for (int np = 0; np < 4; np++) {
                mma_h(c[2 * np],     aq[d8], &bf[np][0]);
                mma_h(c[2 * np + 1], aq[d8], &bf[np][2]);
            }
        }

#pragma unroll
        for (int j = 0; j < 8; j++)
#pragma unroll
            for (int q = 0; q < 4; q++) c[j][q] *= SC;

        if (k0 + 63 > q0 + wid * 16) {
            int rbase = q0 + wid * 16 + (lane >> 2);
#pragma unroll
            for (int j = 0; j < 8; j++) {
                int col = k0 + j * 8 + (lane & 3) * 2;
#pragma unroll
                for (int t = 0; t < 2; t++) {
                    int row = rbase + t * 8;
                    if (col > row)     c[j][2 * t]     = -INFINITY;
                    if (col + 1 > row) c[j][2 * t + 1] = -INFINITY;
                }
            }
        }

#pragma unroll
        for (int t = 0; t < 2; t++) {
            float mx = -INFINITY;
#pragma unroll
            for (int j = 0; j < 8; j++)
                mx = fmaxf(mx, fmaxf(c[j][2 * t], c[j][2 * t + 1]));
            mx = fmaxf(mx, __shfl_xor_sync(0xffffffffu, mx, 1));
            mx = fmaxf(mx, __shfl_xor_sync(0xffffffffu, mx, 2));
            float mnew = fmaxf(m[t], mx);
            float corr = exp2f(m[t] - mnew);
            float rs = 0.f;
#pragma unroll
            for (int j = 0; j < 8; j++) {
                float p0 = exp2f(c[j][2 * t] - mnew);
                float p1 = exp2f(c[j][2 * t + 1] - mnew);
                c[j][2 * t] = p0;
                c[j][2 * t + 1] = p1;
                rs += p0 + p1;
            }
            rs += __shfl_xor_sync(0xffffffffu, rs, 1);
            rs += __shfl_xor_sync(0xffffffffu, rs, 2);
            l[t] = l[t] * corr + rs;
            m[t] = mnew;
#pragma unroll
            for (int nt = 0; nt < 16; nt++) {
                o[nt][2 * t] *= corr;
                o[nt][2 * t + 1] *= corr;
            }
        }

        u32 ph[4][4];
#pragma unroll
        for (int t = 0; t < 4; t++) {
            ph[t][0] = pack_h2(c[2 * t][0], c[2 * t][1]);
            ph[t][1] = pack_h2(c[2 * t][2], c[2 * t][3]);
            ph[t][2] = pack_h2(c[2 * t + 1][0], c[2 * t + 1][1]);
            ph[t][3] = pack_h2(c[2 * t + 1][2], c[2 * t + 1][3]);
        }

#pragma unroll
        for (int t = 0; t < 4; t++) {
            u32 vrow = vbase + v_off + t * (16 * FROWB);
#pragma unroll
            for (int np = 0; np < 8; np++) {
                u32 b0, b1, b2, b3;
                ldmx4t(vrow + np * 32, b0, b1, b2, b3);
                u32 bl[2] = {b0, b1};
                u32 bh[2] = {b2, b3};
                mma_h(o[2 * np], ph[t], bl);
                mma_h(o[2 * np + 1], ph[t], bh);
            }
        }
    }

    float inv0 = 1.0f / l[0], inv1 = 1.0f / l[1];
    long row = q0 + wid * 16 + (lane >> 2);
    int colb = h * HD + (lane & 3) * 2;
#pragma unroll
    for (int nt = 0; nt < 16; nt++) {
        int c = colb + nt * 8;
        *(u32*)((char*)g_Ah + (row * HID + c) * 2) =
            pack_h2(o[nt][0] * inv0, o[nt][1] * inv0);
        *(u32*)((char*)g_Ah + ((row + 8) * HID + c) * 2) =
            pack_h2(o[nt][2] * inv1, o[nt][3] * inv1);
    }
}

// ---------------------------------------------------------------------------
extern "C" void kernel_launch(void* const* d_in, const int* in_sizes, int n_in,
                              void* d_out, int out_size) {
    (void)in_sizes; (void)n_in; (void)out_size;
    const float* x   = (const float*)d_in[0];
    const int*   pos = (const int*)d_in[1];
    const float* wq  = (const float*)d_in[2];
    const float* wk  = (const float*)d_in[3];
    const float* wv  = (const float*)d_in[4];
    const float* wo  = (const float*)d_in[5];
    float* out = (float*)d_out;

    __half *Xh, *Ah;
    cudaGetSymbolAddress((void**)&Xh, g_Xh);
    cudaGetSymbolAddress((void**)&Ah, g_Ah);

    {
        int nx4 = SEQ * HID / 4;
        int nw4 = HID * HID / 4;
        int bx = (nx4 / 2 + 255) / 256;
        int bw = (nw4 / 2 + 255) / 256;
        cvt_x<<<bx, 256>>>((const float4*)x, (uint2*)Xh, nx4);
        cvt_w<<<dim3(bw, 4), 256>>>((const float4*)wq, (const float4*)wk,
                                    (const float4*)wv, (const float4*)wo, nw4);
    }

    cudaFuncSetAttribute(gemm_qkv,
                         cudaFuncAttributeMaxDynamicSharedMemorySize, GEMM_SMEM);
    cudaFuncSetAttribute(gemm_o,
                         cudaFuncAttributeMaxDynamicSharedMemorySize, GEMM_SMEM);
    cudaFuncSetAttribute(flash_h,
                         cudaFuncAttributeMaxDynamicSharedMemorySize, FLASH_SMEM);

    gemm_qkv<<<dim3(32, 16, 3), 256, GEMM_SMEM>>>(Xh, pos);

    flash_h<<<dim3(32, 32), 128, FLASH_SMEM>>>();

    gemm_o<<<dim3(32, 16), 256, GEMM_SMEM>>>(Ah, out);
}